// round 5
// baseline (speedup 1.0000x reference)
#include <cuda_runtime.h>
#include <cstddef>

#define BH 16
#define NSEQ 8192
#define DIM 64
#define MLAND 256
#define KW 33
#define PADW 16

// ---------------- scratch (device globals: allocation-free) ----------------
static __device__ float g_QL[BH*MLAND*DIM];
static __device__ float g_KL[BH*MLAND*DIM];
static __device__ float g_A2[BH*MLAND*MLAND];
static __device__ float g_Z [BH*MLAND*MLAND];
static __device__ float g_Z2[BH*MLAND*MLAND];
static __device__ float g_XZ[BH*MLAND*MLAND];
static __device__ float g_U [BH*MLAND*MLAND];
static __device__ float g_Wm[BH*MLAND*MLAND];
static __device__ float g_S [(size_t)BH*NSEQ*MLAND];   // shared scratch for sim3 then sim1
static __device__ float g_T [BH*MLAND*DIM];
static __device__ float g_W2[BH*MLAND*DIM];
static __device__ float g_m3[BH*MLAND];
static __device__ float g_l3[BH*MLAND];
static __device__ float g_m1[BH*NSEQ];
static __device__ float g_l1[BH*NSEQ];
static __device__ float g_rmax[BH];
static __device__ float g_cmax[BH];

// ---------------- landmarks: mean over contiguous groups of 32 ----------------
__global__ void landmark_kernel(const float* __restrict__ q, const float* __restrict__ k){
    int bh = blockIdx.y, mr = blockIdx.x, c = threadIdx.x;
    const float* qb = q + ((size_t)bh*NSEQ + (size_t)mr*32)*DIM + c;
    const float* kb = k + ((size_t)bh*NSEQ + (size_t)mr*32)*DIM + c;
    float sq = 0.f, sk = 0.f;
#pragma unroll
    for(int t=0;t<32;t++){ sq += qb[(size_t)t*DIM]; sk += kb[(size_t)t*DIM]; }
    g_QL[(bh*MLAND+mr)*DIM+c] = sq*(1.f/32.f);
    g_KL[(bh*MLAND+mr)*DIM+c] = sk*(1.f/32.f);
}

// ---------------- attn2 = softmax(q_land @ k_land^T), fused ----------------
// dynamic smem: transposed KL tile [64][257] (conflict-free both directions)
__global__ void attn2_kernel(){
    extern __shared__ float klt[];           // 64*257 floats
    __shared__ float qr[DIM];
    __shared__ float red[256];
    int bh = blockIdx.y, tid = threadIdx.x;
    for(int p=tid; p<MLAND*DIM; p+=256){
        int j = p>>6, c = p&63;
        klt[c*257+j] = g_KL[(bh*MLAND+j)*DIM+c];
    }
    __syncthreads();
    for(int rr=0; rr<16; rr++){
        int row = blockIdx.x*16 + rr;
        if(tid<DIM) qr[tid] = g_QL[(bh*MLAND+row)*DIM+tid];
        __syncthreads();
        float dot = 0.f;
#pragma unroll
        for(int c=0;c<DIM;c++) dot += qr[c]*klt[c*257+tid];
        red[tid]=dot; __syncthreads();
        for(int s=128;s>0;s>>=1){ if(tid<s) red[tid]=fmaxf(red[tid],red[tid+s]); __syncthreads(); }
        float mx = red[0]; __syncthreads();
        float e = expf(dot-mx);
        red[tid]=e; __syncthreads();
        for(int s=128;s>0;s>>=1){ if(tid<s) red[tid]+=red[tid+s]; __syncthreads(); }
        float sm = red[0]; __syncthreads();
        g_A2[((size_t)bh*MLAND+row)*MLAND+tid] = e/sm;
    }
}

// ---------------- per-bh max row-sum / max col-sum of attn2 ----------------
__global__ void colrow_kernel(){
    __shared__ float red[256];
    int bh = blockIdx.x, tid = threadIdx.x;
    const float* A = g_A2 + (size_t)bh*MLAND*MLAND;
    float cs=0.f, rs=0.f;                    // cs: column sums; rs: row sums
    for(int i=0;i<MLAND;i++) cs += A[(size_t)i*MLAND+tid];
    for(int j=0;j<MLAND;j++) rs += A[(size_t)tid*MLAND+j];
    red[tid]=cs; __syncthreads();
    for(int s=128;s>0;s>>=1){ if(tid<s) red[tid]=fmaxf(red[tid],red[tid+s]); __syncthreads(); }
    if(tid==0) g_cmax[bh]=red[0];
    __syncthreads();
    red[tid]=rs; __syncthreads();
    for(int s=128;s>0;s>>=1){ if(tid<s) red[tid]=fmaxf(red[tid],red[tid+s]); __syncthreads(); }
    if(tid==0) g_rmax[bh]=red[0];
}

// ---------------- z0 = x^T / (global max rowsum * global max colsum) ----------------
__global__ void zinit_kernel(){
    int bh = blockIdx.y, row = blockIdx.x, j = threadIdx.x;
    float mr=0.f, mc=0.f;
#pragma unroll
    for(int t=0;t<BH;t++){ mr=fmaxf(mr,g_rmax[t]); mc=fmaxf(mc,g_cmax[t]); }
    float inv = 1.f/(mr*mc);
    g_Z[((size_t)bh*MLAND+row)*MLAND+j] = g_A2[((size_t)bh*MLAND+j)*MLAND+row]*inv;
}

// ---------------- batched 256x256x256 GEMM: C = dg*I + s*(A@B) + tt*A ----------------
__global__ void mmex_kernel(const float* __restrict__ A, const float* __restrict__ B,
                            float* __restrict__ C, float s, float dg, float tt){
    __shared__ float As[16][65];     // [k][i]
    __shared__ float Bs[16][65];     // [k][j]
    int bh = blockIdx.z;
    A += (size_t)bh*MLAND*MLAND; B += (size_t)bh*MLAND*MLAND; C += (size_t)bh*MLAND*MLAND;
    int i0 = blockIdx.x*64, j0 = blockIdx.y*64;
    int tid = threadIdx.x, tx = tid&15, ty = tid>>4;
    float acc[4][4] = {};
    for(int kk=0; kk<MLAND; kk+=16){
#pragma unroll
        for(int rep=0; rep<4; rep++){
            int p = rep*256+tid;
            int i = p>>4, kq = p&15;
            As[kq][i] = A[(size_t)(i0+i)*MLAND + kk + kq];
            int kb = p>>6, j = p&63;
            Bs[kb][j] = B[(size_t)(kk+kb)*MLAND + j0 + j];
        }
        __syncthreads();
#pragma unroll
        for(int kq=0; kq<16; kq++){
            float a[4], b[4];
#pragma unroll
            for(int r=0;r<4;r++) a[r]=As[kq][ty*4+r];
#pragma unroll
            for(int c=0;c<4;c++) b[c]=Bs[kq][tx*4+c];
#pragma unroll
            for(int r=0;r<4;r++)
#pragma unroll
                for(int c=0;c<4;c++) acc[r][c] += a[r]*b[c];
        }
        __syncthreads();
    }
#pragma unroll
    for(int r=0;r<4;r++){
        int gi = i0+ty*4+r;
#pragma unroll
        for(int c=0;c<4;c++){
            int gj = j0+tx*4+c;
            float val = s*acc[r][c];
            if(gi==gj) val += dg;
            if(tt!=0.f) val += tt*A[(size_t)gi*MLAND+gj];
            C[(size_t)gi*MLAND+gj] = val;
        }
    }
}

// ---------------- NT gemm (K=64): C[i,j] = sum_c A[i,c]*B[j,c] ----------------
__global__ void gemm_nt_kernel(const float* __restrict__ A, const float* __restrict__ B,
                               float* __restrict__ C, int Mr, int Nr){
    __shared__ float As[64][65];     // [c][i]
    __shared__ float Bs[64][65];     // [c][j]
    int bh = blockIdx.z;
    A += (size_t)bh*Mr*DIM; B += (size_t)bh*Nr*DIM; C += (size_t)bh*Mr*Nr;
    int i0 = blockIdx.x*64, j0 = blockIdx.y*64;
    int tid = threadIdx.x, tx = tid&15, ty = tid>>4;
#pragma unroll
    for(int rep=0; rep<16; rep++){
        int p = rep*256+tid; int r = p>>6, c = p&63;
        As[c][r] = A[(size_t)(i0+r)*DIM + c];
        Bs[c][r] = B[(size_t)(j0+r)*DIM + c];
    }
    __syncthreads();
    float acc[4][4] = {};
#pragma unroll 8
    for(int c=0; c<DIM; c++){
        float a[4], b[4];
#pragma unroll
        for(int r=0;r<4;r++) a[r]=As[c][ty*4+r];
#pragma unroll
        for(int cc=0;cc<4;cc++) b[cc]=Bs[c][tx*4+cc];
#pragma unroll
        for(int r=0;r<4;r++)
#pragma unroll
            for(int cc=0;cc<4;cc++) acc[r][cc] += a[r]*b[cc];
    }
#pragma unroll
    for(int r=0;r<4;r++)
#pragma unroll
        for(int cc=0;cc<4;cc++)
            C[(size_t)(i0+ty*4+r)*Nr + j0+tx*4+cc] = acc[r][cc];
}

// ---------------- per-row softmax stats (max, 1/sumexp) ----------------
__global__ void stats_kernel(const float* __restrict__ S, float* __restrict__ mo,
                             float* __restrict__ lo, int W){
    __shared__ float red[256];
    size_t row = blockIdx.x;
    const float* Sr = S + row*(size_t)W;
    int tid = threadIdx.x;
    float mx = -1e30f;
    for(int j=tid;j<W;j+=256) mx = fmaxf(mx, Sr[j]);
    red[tid]=mx; __syncthreads();
    for(int s=128;s>0;s>>=1){ if(tid<s) red[tid]=fmaxf(red[tid],red[tid+s]); __syncthreads(); }
    mx = red[0]; __syncthreads();
    float sm = 0.f;
    for(int j=tid;j<W;j+=256) sm += expf(Sr[j]-mx);
    red[tid]=sm; __syncthreads();
    for(int s=128;s>0;s>>=1){ if(tid<s) red[tid]+=red[tid+s]; __syncthreads(); }
    if(tid==0){ mo[row]=mx; lo[row]=1.f/red[0]; }
}

// ---------------- C[rows,64] = softmax?(A[rows,K]) @ B[K,64], batched over bh ----------------
// 32 rows/block; each thread: 4 rows x 2 cols register tile
__global__ void ab_kernel(const float* __restrict__ A, const float* __restrict__ mo,
                          const float* __restrict__ lo, const float* __restrict__ B,
                          float* __restrict__ C, int rows, int K){
    __shared__ float Vs[64][64];
    __shared__ float Ss[32][64];
    int bh = blockIdx.y;
    const float* Ab = A + (size_t)bh*rows*K;
    const float* Bb = B + (size_t)bh*K*DIM;
    float*       Cb = C + (size_t)bh*rows*DIM;
    int r0 = blockIdx.x*32;
    int tid = threadIdx.x;
    int d = tid&31, ig = tid>>5;             // ig 0..7
    float acc[4][2] = {};
    for(int kt=0; kt<K; kt+=64){
#pragma unroll
        for(int rep=0; rep<16; rep++){
            int p = rep*256+tid; int j = p>>6, c = p&63;
            Vs[j][c] = Bb[(size_t)(kt+j)*DIM + c];
        }
#pragma unroll
        for(int rep=0; rep<8; rep++){
            int p = rep*256+tid; int rr = p>>6, jj = p&63;
            float sval = Ab[(size_t)(r0+rr)*K + kt + jj];
            if(mo){ int gr = bh*rows + r0 + rr; sval = expf(sval - mo[gr])*lo[gr]; }
            Ss[rr][jj] = sval;
        }
        __syncthreads();
#pragma unroll 4
        for(int j=0;j<64;j++){
            float v0 = Vs[j][d], v1 = Vs[j][d+32];
#pragma unroll
            for(int r=0;r<4;r++){
                float sv = Ss[ig+8*r][j];
                acc[r][0] += sv*v0;
                acc[r][1] += sv*v1;
            }
        }
        __syncthreads();
    }
#pragma unroll
    for(int r=0;r<4;r++){
        Cb[(size_t)(r0+ig+8*r)*DIM + d]      = acc[r][0];
        Cb[(size_t)(r0+ig+8*r)*DIM + d + 32] = acc[r][1];
    }
}

// ---------------- depthwise residual conv over seq dim: out += conv(v) ----------------
__global__ void conv_kernel(const float* __restrict__ v, const float* __restrict__ cw,
                            float* __restrict__ out){
    __shared__ float vt[64][64];
    __shared__ float ws[KW];
    int bh = blockIdx.y;
    int i0 = blockIdx.x*32;
    int tid = threadIdx.x;
    if(tid<KW) ws[tid] = cw[(bh&7)*KW + tid];
#pragma unroll
    for(int rep=0; rep<16; rep++){
        int p = rep*256+tid; int r = p>>6, c = p&63;
        int gr = i0 - PADW + r;
        vt[r][c] = (gr>=0 && gr<NSEQ) ? v[((size_t)bh*NSEQ+gr)*DIM + c] : 0.f;
    }
    __syncthreads();
    int d = tid&63, ib = tid>>6;
#pragma unroll
    for(int t=0;t<8;t++){
        int il = ib + 4*t;
        float acc = 0.f;
#pragma unroll
        for(int kk=0; kk<KW; kk++) acc += ws[kk]*vt[il+kk][d];
        size_t oi = ((size_t)bh*NSEQ + i0 + il)*DIM + d;
        out[oi] += acc;
    }
}

// ---------------- launch ----------------
extern "C" void kernel_launch(void* const* d_in, const int* in_sizes, int n_in,
                              void* d_out, int out_size){
    const float* q  = (const float*)d_in[0];
    const float* k  = (const float*)d_in[1];
    const float* v  = (const float*)d_in[2];
    const float* cw = (const float*)d_in[3];
    float* out = (float*)d_out;

    float *pQL,*pKL,*pA2,*pZ,*pZ2,*pXZ,*pU,*pWm,*pS,*pT,*pW2,*pm3,*pl3,*pm1,*pl1;
    cudaGetSymbolAddress((void**)&pQL, g_QL);
    cudaGetSymbolAddress((void**)&pKL, g_KL);
    cudaGetSymbolAddress((void**)&pA2, g_A2);
    cudaGetSymbolAddress((void**)&pZ,  g_Z);
    cudaGetSymbolAddress((void**)&pZ2, g_Z2);
    cudaGetSymbolAddress((void**)&pXZ, g_XZ);
    cudaGetSymbolAddress((void**)&pU,  g_U);
    cudaGetSymbolAddress((void**)&pWm, g_Wm);
    cudaGetSymbolAddress((void**)&pS,  g_S);
    cudaGetSymbolAddress((void**)&pT,  g_T);
    cudaGetSymbolAddress((void**)&pW2, g_W2);
    cudaGetSymbolAddress((void**)&pm3, g_m3);
    cudaGetSymbolAddress((void**)&pl3, g_l3);
    cudaGetSymbolAddress((void**)&pm1, g_m1);
    cudaGetSymbolAddress((void**)&pl1, g_l1);

    cudaFuncSetAttribute(attn2_kernel, cudaFuncAttributeMaxDynamicSharedMemorySize, 64*257*4);

    // landmarks + attn2 + pinv init
    landmark_kernel<<<dim3(MLAND,BH), DIM>>>(q, k);
    attn2_kernel<<<dim3(16,BH), 256, 64*257*4>>>();
    colrow_kernel<<<BH, 256>>>();
    zinit_kernel<<<dim3(MLAND,BH), 256>>>();

    // 6 Moore-Penrose iterations (4 fused GEMMs each):
    //   XZ = x@z ; U = 15I - 7*XZ + XZ@XZ ; Wm = 13I - XZ@U ; z' = 0.25*z@Wm
    float* zc = pZ; float* zn = pZ2;
    for(int it=0; it<6; it++){
        mmex_kernel<<<dim3(4,4,BH), 256>>>(pA2, zc, pXZ, 1.f,  0.f,  0.f);
        mmex_kernel<<<dim3(4,4,BH), 256>>>(pXZ, pXZ, pU, 1.f, 15.f, -7.f);
        mmex_kernel<<<dim3(4,4,BH), 256>>>(pXZ, pU, pWm, -1.f, 13.f, 0.f);
        mmex_kernel<<<dim3(4,4,BH), 256>>>(zc,  pWm, zn, 0.25f, 0.f, 0.f);
        float* tsw = zc; zc = zn; zn = tsw;
    }
    // after 6 iterations result is back in g_Z (zc)

    // sim3 path: T = softmax(q_land@k^T) @ v
    gemm_nt_kernel<<<dim3(MLAND/64, NSEQ/64, BH), 256>>>(pQL, k, pS, MLAND, NSEQ);
    stats_kernel<<<BH*MLAND, 256>>>(pS, pm3, pl3, NSEQ);
    ab_kernel<<<dim3(MLAND/32, BH), 256>>>(pS, pm3, pl3, v, pT, MLAND, NSEQ);

    // W2 = attn2_inv @ T
    ab_kernel<<<dim3(MLAND/32, BH), 256>>>(zc, nullptr, nullptr, pT, pW2, MLAND, MLAND);

    // sim1 path: out = softmax(q@k_land^T) @ W2
    gemm_nt_kernel<<<dim3(NSEQ/64, MLAND/64, BH), 256>>>(q, pKL, pS, NSEQ, MLAND);
    stats_kernel<<<BH*NSEQ, 256>>>(pS, pm1, pl1, MLAND);
    ab_kernel<<<dim3(NSEQ/32, BH), 256>>>(pS, pm1, pl1, pW2, out, NSEQ, MLAND);

    // residual depthwise conv
    conv_kernel<<<dim3(NSEQ/32, BH), 256>>>(v, cw, out);
}

// round 8
// speedup vs baseline: 1.5033x; 1.5033x over previous
#include <cuda_runtime.h>
#include <cstddef>

#define BH 16
#define NSEQ 8192
#define DIM 64
#define MLAND 256
#define KW 33
#define PADW 16
#define NSPLIT 8
#define SPLEN (NSEQ/NSPLIT)   // 1024

// ---------------- scratch (device globals: allocation-free) ----------------
static __device__ float g_QL[BH*MLAND*DIM];
static __device__ float g_KL[BH*MLAND*DIM];
static __device__ float g_A2[BH*MLAND*MLAND];
static __device__ float g_Z [BH*MLAND*MLAND];
static __device__ float g_Z2[BH*MLAND*MLAND];
static __device__ float g_XZ[BH*MLAND*MLAND];
static __device__ float g_U [BH*MLAND*MLAND];
static __device__ float g_Wm[BH*MLAND*MLAND];
static __device__ float g_T [BH*MLAND*DIM];
static __device__ float g_W2[BH*MLAND*DIM];
static __device__ float g_pacc[BH*4*NSPLIT*64*64];   // flash partial outputs (8.4 MB)
static __device__ float g_pm [BH*4*NSPLIT*64];
static __device__ float g_pl [BH*4*NSPLIT*64];
static __device__ float g_rmax[BH];
static __device__ float g_cmax[BH];

// ---------------- landmarks: mean over contiguous groups of 32 ----------------
__global__ void landmark_kernel(const float* __restrict__ q, const float* __restrict__ k){
    int bh = blockIdx.y, mr = blockIdx.x, c = threadIdx.x;
    const float* qb = q + ((size_t)bh*NSEQ + (size_t)mr*32)*DIM + c;
    const float* kb = k + ((size_t)bh*NSEQ + (size_t)mr*32)*DIM + c;
    float sq = 0.f, sk = 0.f;
#pragma unroll
    for(int t=0;t<32;t++){ sq += qb[(size_t)t*DIM]; sk += kb[(size_t)t*DIM]; }
    g_QL[(bh*MLAND+mr)*DIM+c] = sq*(1.f/32.f);
    g_KL[(bh*MLAND+mr)*DIM+c] = sk*(1.f/32.f);
}

// ---------------- attn2 = softmax(q_land @ k_land^T), fused ----------------
__global__ void attn2_kernel(){
    extern __shared__ float klt[];           // 64*257 floats
    __shared__ float qr[DIM];
    __shared__ float red[256];
    int bh = blockIdx.y, tid = threadIdx.x;
    for(int p=tid; p<MLAND*DIM; p+=256){
        int j = p>>6, c = p&63;
        klt[c*257+j] = g_KL[(bh*MLAND+j)*DIM+c];
    }
    __syncthreads();
    for(int rr=0; rr<16; rr++){
        int row = blockIdx.x*16 + rr;
        if(tid<DIM) qr[tid] = g_QL[(bh*MLAND+row)*DIM+tid];
        __syncthreads();
        float dot = 0.f;
#pragma unroll
        for(int c=0;c<DIM;c++) dot += qr[c]*klt[c*257+tid];
        red[tid]=dot; __syncthreads();
        for(int s=128;s>0;s>>=1){ if(tid<s) red[tid]=fmaxf(red[tid],red[tid+s]); __syncthreads(); }
        float mx = red[0]; __syncthreads();
        float e = expf(dot-mx);
        red[tid]=e; __syncthreads();
        for(int s=128;s>0;s>>=1){ if(tid<s) red[tid]+=red[tid+s]; __syncthreads(); }
        float sm = red[0]; __syncthreads();
        g_A2[((size_t)bh*MLAND+row)*MLAND+tid] = e/sm;
    }
}

// ---------------- per-bh max row-sum / max col-sum of attn2 ----------------
__global__ void colrow_kernel(){
    __shared__ float red[256];
    int bh = blockIdx.x, tid = threadIdx.x;
    const float* A = g_A2 + (size_t)bh*MLAND*MLAND;
    float cs=0.f, rs=0.f;
    for(int i=0;i<MLAND;i++) cs += A[(size_t)i*MLAND+tid];
    for(int j=0;j<MLAND;j++) rs += A[(size_t)tid*MLAND+j];
    red[tid]=cs; __syncthreads();
    for(int s=128;s>0;s>>=1){ if(tid<s) red[tid]=fmaxf(red[tid],red[tid+s]); __syncthreads(); }
    if(tid==0) g_cmax[bh]=red[0];
    __syncthreads();
    red[tid]=rs; __syncthreads();
    for(int s=128;s>0;s>>=1){ if(tid<s) red[tid]=fmaxf(red[tid],red[tid+s]); __syncthreads(); }
    if(tid==0) g_rmax[bh]=red[0];
}

// ---------------- z0 = x^T * inv, coalesced via smem tile transpose ----------------
__global__ void zinit_kernel(){
    __shared__ float tile[64*65];
    int bh = blockIdx.z;
    int i0 = blockIdx.x*64, j0 = blockIdx.y*64;
    int tid = threadIdx.x;
#pragma unroll
    for(int rep=0; rep<16; rep++){
        int p = rep*256+tid; int r = p>>6, c = p&63;
        tile[r*65+c] = g_A2[((size_t)bh*MLAND + i0+r)*MLAND + j0+c];
    }
    __syncthreads();
    float mr=0.f, mc=0.f;
#pragma unroll
    for(int t=0;t<BH;t++){ mr=fmaxf(mr,g_rmax[t]); mc=fmaxf(mc,g_cmax[t]); }
    float inv = 1.f/(mr*mc);
#pragma unroll
    for(int rep=0; rep<16; rep++){
        int p = rep*256+tid; int r = p>>6, c = p&63;
        g_Z[((size_t)bh*MLAND + j0+r)*MLAND + i0+c] = tile[c*65+r]*inv;
    }
}

// ---------------- batched 256x256x256 GEMM: C = dg*I + s*(A@B) + tt*A ----------------
__global__ void mmex_kernel(const float* __restrict__ A, const float* __restrict__ B,
                            float* __restrict__ C, float s, float dg, float tt){
    __shared__ float As[16][65];
    __shared__ float Bs[16][65];
    int bh = blockIdx.z;
    A += (size_t)bh*MLAND*MLAND; B += (size_t)bh*MLAND*MLAND; C += (size_t)bh*MLAND*MLAND;
    int i0 = blockIdx.x*64, j0 = blockIdx.y*64;
    int tid = threadIdx.x, tx = tid&15, ty = tid>>4;
    float acc[4][4] = {};
    for(int kk=0; kk<MLAND; kk+=16){
#pragma unroll
        for(int rep=0; rep<4; rep++){
            int p = rep*256+tid;
            int i = p>>4, kq = p&15;
            As[kq][i] = A[(size_t)(i0+i)*MLAND + kk + kq];
            int kb = p>>6, j = p&63;
            Bs[kb][j] = B[(size_t)(kk+kb)*MLAND + j0 + j];
        }
        __syncthreads();
#pragma unroll
        for(int kq=0; kq<16; kq++){
            float a[4], b[4];
#pragma unroll
            for(int r=0;r<4;r++) a[r]=As[kq][ty*4+r];
#pragma unroll
            for(int c=0;c<4;c++) b[c]=Bs[kq][tx*4+c];
#pragma unroll
            for(int r=0;r<4;r++)
#pragma unroll
                for(int c=0;c<4;c++) acc[r][c] += a[r]*b[c];
        }
        __syncthreads();
    }
#pragma unroll
    for(int r=0;r<4;r++){
        int gi = i0+ty*4+r;
#pragma unroll
        for(int c=0;c<4;c++){
            int gj = j0+tx*4+c;
            float val = s*acc[r][c];
            if(gi==gj) val += dg;
            if(tt!=0.f) val += tt*A[(size_t)gi*MLAND+gj];
            C[(size_t)gi*MLAND+gj] = val;
        }
    }
}

// ---------------- sim3 flash: partial T = onlinesoftmax(QL@k^T)@v over a key split ----------------
// grid (4 qblk, NSPLIT, BH), 256 threads, dyn smem 4*64*65 floats
__global__ void flash3_kernel(const float* __restrict__ k, const float* __restrict__ v){
    extern __shared__ float sm_[];
    float* qs = sm_;              // [c][i] 64x65
    float* kt = qs + 64*65;       // [c][j] 64x65
    float* vs = kt + 64*65;       // [j][d] 64x65
    float* Ps = vs + 64*65;       // [j][i] 64x65
    int qb = blockIdx.x, sp = blockIdx.y, bh = blockIdx.z;
    int tid = threadIdx.x, tx = tid&15, ty = tid>>4;
#pragma unroll
    for(int rep=0; rep<16; rep++){
        int p = rep*256+tid; int r = p>>6, c = p&63;
        qs[c*65+r] = g_QL[((size_t)bh*MLAND + qb*64 + r)*DIM + c];
    }
    float m[4], l[4], acc[4][4];
#pragma unroll
    for(int r=0;r<4;r++){ m[r]=-1e30f; l[r]=0.f;
#pragma unroll
        for(int c=0;c<4;c++) acc[r][c]=0.f; }
    for(int t=0; t<SPLEN/64; t++){
        int j0 = sp*SPLEN + t*64;
#pragma unroll
        for(int rep=0; rep<16; rep++){
            int p = rep*256+tid; int r = p>>6, c = p&63;
            kt[c*65+r] = k[((size_t)bh*NSEQ + j0+r)*DIM + c];
            vs[r*65+c] = v[((size_t)bh*NSEQ + j0+r)*DIM + c];
        }
        __syncthreads();
        float s[4][4] = {};
#pragma unroll 8
        for(int c=0;c<DIM;c++){
            float a[4], b[4];
#pragma unroll
            for(int r=0;r<4;r++) a[r]=qs[c*65+ty*4+r];
#pragma unroll
            for(int cc=0;cc<4;cc++) b[cc]=kt[c*65+tx*4+cc];
#pragma unroll
            for(int r=0;r<4;r++)
#pragma unroll
                for(int cc=0;cc<4;cc++) s[r][cc] += a[r]*b[cc];
        }
#pragma unroll
        for(int r=0;r<4;r++){
            float tmax = fmaxf(fmaxf(s[r][0],s[r][1]), fmaxf(s[r][2],s[r][3]));
#pragma unroll
            for(int o=1;o<16;o<<=1) tmax = fmaxf(tmax, __shfl_xor_sync(0xffffffffu, tmax, o));
            float mn = fmaxf(m[r], tmax);
            float scale = expf(m[r]-mn);
            float p0[4], rs = 0.f;
#pragma unroll
            for(int cc=0;cc<4;cc++){ p0[cc] = expf(s[r][cc]-mn); rs += p0[cc]; }
#pragma unroll
            for(int o=1;o<16;o<<=1) rs += __shfl_xor_sync(0xffffffffu, rs, o);
            l[r] = l[r]*scale + rs;
            m[r] = mn;
#pragma unroll
            for(int cc=0;cc<4;cc++){
                acc[r][cc] *= scale;
                Ps[(tx*4+cc)*65 + ty*4+r] = p0[cc];
            }
        }
        __syncthreads();
#pragma unroll 4
        for(int j=0;j<64;j++){
            float a[4], b[4];
#pragma unroll
            for(int r=0;r<4;r++) a[r]=Ps[j*65+ty*4+r];
#pragma unroll
            for(int cc=0;cc<4;cc++) b[cc]=vs[j*65+tx*4+cc];
#pragma unroll
            for(int r=0;r<4;r++)
#pragma unroll
                for(int cc=0;cc<4;cc++) acc[r][cc] += a[r]*b[cc];
        }
        __syncthreads();
    }
    int base = ((bh*4+qb)*NSPLIT + sp);
#pragma unroll
    for(int r=0;r<4;r++){
        int i = ty*4+r;
#pragma unroll
        for(int cc=0;cc<4;cc++)
            g_pacc[((size_t)base*64 + i)*64 + tx*4+cc] = acc[r][cc];
        if(tx==0){ g_pm[base*64+i]=m[r]; g_pl[base*64+i]=l[r]; }
    }
}

// ---------------- merge flash partials -> g_T ----------------
// grid 64 (= bh*4+qb), 256 threads: thread handles row i=tid>>2, 16 dims
__global__ void merge3_kernel(){
    int bq = blockIdx.x;
    int tid = threadIdx.x;
    int i = tid>>2, g = tid&3;
    float M = -1e30f;
#pragma unroll
    for(int s=0;s<NSPLIT;s++) M = fmaxf(M, g_pm[(bq*NSPLIT+s)*64 + i]);
    float L = 0.f;
#pragma unroll
    for(int s=0;s<NSPLIT;s++) L += g_pl[(bq*NSPLIT+s)*64 + i]*expf(g_pm[(bq*NSPLIT+s)*64+i]-M);
    float invL = 1.f/L;
    float o[16];
#pragma unroll
    for(int d=0;d<16;d++) o[d]=0.f;
#pragma unroll
    for(int s=0;s<NSPLIT;s++){
        float w = expf(g_pm[(bq*NSPLIT+s)*64+i]-M);
        const float* pa = &g_pacc[((size_t)(bq*NSPLIT+s)*64 + i)*64 + g*16];
#pragma unroll
        for(int d=0;d<16;d++) o[d] += w*pa[d];
    }
    int bh = bq>>2, qb = bq&3;
    float* To = &g_T[((size_t)bh*MLAND + qb*64 + i)*DIM + g*16];
#pragma unroll
    for(int d=0;d<16;d++) To[d] = o[d]*invL;
}

// ---------------- C[rows,64] = A[rows,K] @ B[K,64] (used for W2 = Z @ T) ----------------
__global__ void ab_kernel(const float* __restrict__ A, const float* __restrict__ B,
                          float* __restrict__ C, int rows, int K){
    __shared__ float Vs[64][64];
    __shared__ float Ss[32][64];
    int bh = blockIdx.y;
    const float* Ab = A + (size_t)bh*rows*K;
    const float* Bb = B + (size_t)bh*K*DIM;
    float*       Cb = C + (size_t)bh*rows*DIM;
    int r0 = blockIdx.x*32;
    int tid = threadIdx.x;
    int d = tid&31, ig = tid>>5;
    float acc[4][2] = {};
    for(int kt=0; kt<K; kt+=64){
#pragma unroll
        for(int rep=0; rep<16; rep++){
            int p = rep*256+tid; int j = p>>6, c = p&63;
            Vs[j][c] = Bb[(size_t)(kt+j)*DIM + c];
        }
#pragma unroll
        for(int rep=0; rep<8; rep++){
            int p = rep*256+tid; int rr = p>>6, jj = p&63;
            Ss[rr][jj] = Ab[(size_t)(r0+rr)*K + kt + jj];
        }
        __syncthreads();
#pragma unroll 4
        for(int j=0;j<64;j++){
            float v0 = Vs[j][d], v1 = Vs[j][d+32];
#pragma unroll
            for(int r=0;r<4;r++){
                float sv = Ss[ig+8*r][j];
                acc[r][0] += sv*v0;
                acc[r][1] += sv*v1;
            }
        }
        __syncthreads();
    }
#pragma unroll
    for(int r=0;r<4;r++){
        Cb[(size_t)(r0+ig+8*r)*DIM + d]      = acc[r][0];
        Cb[(size_t)(r0+ig+8*r)*DIM + d + 32] = acc[r][1];
    }
}

// ---------------- sim1 fused: out = softmax(q@KL^T) @ W2 + conv(v) ----------------
// grid (128, BH), 256 threads, dyn smem (64*257 + 2*64*65) floats
__global__ void fused1_kernel(const float* __restrict__ q, const float* __restrict__ v,
                              const float* __restrict__ cw, float* __restrict__ out){
    extern __shared__ float sm_[];
    float* Ss = sm_;              // [i][j] 64x257 score block
    float* As = Ss + 64*257;      // [c][i] 64x65 q transposed
    float* Bs = As + 64*65;       // 64x65  KL tile / W2 tile
    float* Vv = As;               // conv reuse: 96x65 floats (fits in As+Bs = 8320)
    __shared__ float ws[KW];
    int bh = blockIdx.y;
    int r0 = blockIdx.x*64;
    int tid = threadIdx.x, tx = tid&15, ty = tid>>4;
    if(tid<KW) ws[tid] = cw[(bh&7)*KW + tid];
#pragma unroll
    for(int rep=0; rep<16; rep++){
        int p = rep*256+tid; int r = p>>6, c = p&63;
        As[c*65+r] = q[((size_t)bh*NSEQ + r0+r)*DIM + c];
    }
    // phase 1: S = q @ KL^T, 4 column tiles
    for(int jt=0; jt<4; jt++){
#pragma unroll
        for(int rep=0; rep<16; rep++){
            int p = rep*256+tid; int r = p>>6, c = p&63;
            Bs[c*65+r] = g_KL[((size_t)bh*MLAND + jt*64 + r)*DIM + c];
        }
        __syncthreads();
        float sacc[4][4] = {};
#pragma unroll 8
        for(int c=0;c<DIM;c++){
            float a[4], b[4];
#pragma unroll
            for(int r=0;r<4;r++) a[r]=As[c*65+ty*4+r];
#pragma unroll
            for(int cc=0;cc<4;cc++) b[cc]=Bs[c*65+tx*4+cc];
#pragma unroll
            for(int r=0;r<4;r++)
#pragma unroll
                for(int cc=0;cc<4;cc++) sacc[r][cc] += a[r]*b[cc];
        }
#pragma unroll
        for(int r=0;r<4;r++)
#pragma unroll
            for(int cc=0;cc<4;cc++)
                Ss[(ty*4+r)*257 + jt*64 + tx*4+cc] = sacc[r][cc];
        __syncthreads();
    }
    // phase 2: row softmax (4 threads per row)
    {
        int row = tid>>2, l4 = tid&3;
        float mx = -1e30f;
#pragma unroll
        for(int t=0;t<64;t++) mx = fmaxf(mx, Ss[row*257 + l4 + 4*t]);
        mx = fmaxf(mx, __shfl_xor_sync(0xffffffffu, mx, 1));
        mx = fmaxf(mx, __shfl_xor_sync(0xffffffffu, mx, 2));
        float sm = 0.f;
#pragma unroll
        for(int t=0;t<64;t++){
            int idx = row*257 + l4 + 4*t;
            float e = expf(Ss[idx]-mx);
            Ss[idx] = e;
            sm += e;
        }
        sm += __shfl_xor_sync(0xffffffffu, sm, 1);
        sm += __shfl_xor_sync(0xffffffffu, sm, 2);
        float inv = 1.f/sm;
#pragma unroll
        for(int t=0;t<64;t++) Ss[row*257 + l4 + 4*t] *= inv;
    }
    __syncthreads();
    // phase 3: out = P @ W2
    float oacc[4][4] = {};
    for(int jt=0; jt<4; jt++){
#pragma unroll
        for(int rep=0; rep<16; rep++){
            int p = rep*256+tid; int r = p>>6, c = p&63;
            Bs[r*65+c] = g_W2[((size_t)bh*MLAND + jt*64 + r)*DIM + c];
        }
        __syncthreads();
#pragma unroll 4
        for(int jj=0;jj<64;jj++){
            float a[4], b[4];
#pragma unroll
            for(int r=0;r<4;r++) a[r]=Ss[(ty*4+r)*257 + jt*64+jj];
#pragma unroll
            for(int cc=0;cc<4;cc++) b[cc]=Bs[jj*65 + tx*4+cc];
#pragma unroll
            for(int r=0;r<4;r++)
#pragma unroll
                for(int cc=0;cc<4;cc++) oacc[r][cc] += a[r]*b[cc];
        }
        __syncthreads();
    }
    // phase 4: conv residual + write
#pragma unroll
    for(int rep=0; rep<24; rep++){
        int p = rep*256+tid; int rr = p>>6, c = p&63;
        int gr = r0 - PADW + rr;
        Vv[rr*65+c] = (gr>=0 && gr<NSEQ) ? v[((size_t)bh*NSEQ+gr)*DIM + c] : 0.f;
    }
    __syncthreads();
#pragma unroll
    for(int r=0;r<4;r++){
        int i = ty*4+r;
#pragma unroll
        for(int cc=0;cc<4;cc++){
            int d = tx*4+cc;
            float cacc = 0.f;
#pragma unroll
            for(int kk=0; kk<KW; kk++) cacc += ws[kk]*Vv[(i+kk)*65 + d];
            out[((size_t)bh*NSEQ + r0 + i)*DIM + d] = oacc[r][cc] + cacc;
        }
    }
}

// ---------------- launch ----------------
extern "C" void kernel_launch(void* const* d_in, const int* in_sizes, int n_in,
                              void* d_out, int out_size){
    const float* q  = (const float*)d_in[0];
    const float* k  = (const float*)d_in[1];
    const float* v  = (const float*)d_in[2];
    const float* cw = (const float*)d_in[3];
    float* out = (float*)d_out;

    float *pA2,*pZ,*pZ2,*pXZ,*pU,*pWm,*pT,*pW2;
    cudaGetSymbolAddress((void**)&pA2, g_A2);
    cudaGetSymbolAddress((void**)&pZ,  g_Z);
    cudaGetSymbolAddress((void**)&pZ2, g_Z2);
    cudaGetSymbolAddress((void**)&pXZ, g_XZ);
    cudaGetSymbolAddress((void**)&pU,  g_U);
    cudaGetSymbolAddress((void**)&pWm, g_Wm);
    cudaGetSymbolAddress((void**)&pT,  g_T);
    cudaGetSymbolAddress((void**)&pW2, g_W2);

    cudaFuncSetAttribute(attn2_kernel,  cudaFuncAttributeMaxDynamicSharedMemorySize, 64*257*4);
    cudaFuncSetAttribute(flash3_kernel, cudaFuncAttributeMaxDynamicSharedMemorySize, 4*64*65*4);
    cudaFuncSetAttribute(fused1_kernel, cudaFuncAttributeMaxDynamicSharedMemorySize, (64*257 + 2*64*65)*4);

    // landmarks + attn2 + pinv init
    landmark_kernel<<<dim3(MLAND,BH), DIM>>>(q, k);
    attn2_kernel<<<dim3(16,BH), 256, 64*257*4>>>();
    colrow_kernel<<<BH, 256>>>();
    zinit_kernel<<<dim3(4,4,BH), 256>>>();

    // 6 Moore-Penrose iterations (4 fused GEMMs each)
    float* zc = pZ; float* zn = pZ2;
    for(int it=0; it<6; it++){
        mmex_kernel<<<dim3(4,4,BH), 256>>>(pA2, zc, pXZ, 1.f,  0.f,  0.f);
        mmex_kernel<<<dim3(4,4,BH), 256>>>(pXZ, pXZ, pU, 1.f, 15.f, -7.f);
        mmex_kernel<<<dim3(4,4,BH), 256>>>(pXZ, pU, pWm, -1.f, 13.f, 0.f);
        mmex_kernel<<<dim3(4,4,BH), 256>>>(zc,  pWm, zn, 0.25f, 0.f, 0.f);
        float* tsw = zc; zc = zn; zn = tsw;
    }

    // sim3: T = softmax(QL@k^T) @ v  via split-KV flash + merge
    flash3_kernel<<<dim3(4,NSPLIT,BH), 256, 4*64*65*4>>>(k, v);
    merge3_kernel<<<BH*4, 256>>>();

    // W2 = Z @ T
    ab_kernel<<<dim3(MLAND/32, BH), 256>>>(zc, pT, pW2, MLAND, MLAND);

    // sim1 fused: out = softmax(q@KL^T) @ W2 + conv residual
    fused1_kernel<<<dim3(NSEQ/64, BH), 256, (64*257 + 2*64*65)*4>>>(q, v, cw, out);
}

// round 9
// speedup vs baseline: 1.7210x; 1.1449x over previous
#include <cuda_runtime.h>
#include <cstddef>

#define BH 16
#define NSEQ 8192
#define DIM 64
#define MLAND 256
#define KW 33
#define PADW 16
#define NSPLIT 8
#define SPLEN (NSEQ/NSPLIT)   // 1024

typedef unsigned long long ull;

// ---------------- f32x2 packed-FMA helpers (sm_103a FFMA2) ----------------
#define FMA2(d,a,b,c) asm("fma.rn.f32x2 %0, %1, %2, %3;" : "=l"(d) : "l"(a), "l"(b), "l"(c))
#define MUL2(d,a,b)   asm("mul.rn.f32x2 %0, %1, %2;"     : "=l"(d) : "l"(a), "l"(b))
#define ADD2(d,a,b)   asm("add.rn.f32x2 %0, %1, %2;"     : "=l"(d) : "l"(a), "l"(b))
__device__ __forceinline__ ull dup2(float x){ ull r; asm("mov.b64 %0, {%1, %1};" : "=l"(r) : "f"(x)); return r; }
__device__ __forceinline__ ull pk2(float lo, float hi){ ull r; asm("mov.b64 %0, {%1, %2};" : "=l"(r) : "f"(lo), "f"(hi)); return r; }
__device__ __forceinline__ void unpk(ull p, float& lo, float& hi){ asm("mov.b64 {%0, %1}, %2;" : "=f"(lo), "=f"(hi) : "l"(p)); }
__device__ __forceinline__ ull ld64s(const float* p){ return *reinterpret_cast<const ull*>(p); }

// ---------------- scratch (device globals: allocation-free) ----------------
static __device__ float g_QL[BH*MLAND*DIM];
static __device__ float g_KL[BH*MLAND*DIM];
static __device__ float g_A2[BH*MLAND*MLAND];
static __device__ float g_Z [BH*MLAND*MLAND];
static __device__ float g_Z2[BH*MLAND*MLAND];
static __device__ float g_XZ[BH*MLAND*MLAND];
static __device__ float g_U [BH*MLAND*MLAND];
static __device__ float g_Wm[BH*MLAND*MLAND];
static __device__ float g_T [BH*MLAND*DIM];
static __device__ float g_W2[BH*MLAND*DIM];
static __device__ float g_pacc[BH*4*NSPLIT*64*64];
static __device__ float g_pm [BH*4*NSPLIT*64];
static __device__ float g_pl [BH*4*NSPLIT*64];
static __device__ float g_rmax[BH];
static __device__ float g_cmax[BH];

// ---------------- landmarks ----------------
__global__ void landmark_kernel(const float* __restrict__ q, const float* __restrict__ k){
    int bh = blockIdx.y, mr = blockIdx.x, c = threadIdx.x;
    const float* qb = q + ((size_t)bh*NSEQ + (size_t)mr*32)*DIM + c;
    const float* kb = k + ((size_t)bh*NSEQ + (size_t)mr*32)*DIM + c;
    float sq = 0.f, sk = 0.f;
#pragma unroll
    for(int t=0;t<32;t++){ sq += qb[(size_t)t*DIM]; sk += kb[(size_t)t*DIM]; }
    g_QL[(bh*MLAND+mr)*DIM+c] = sq*(1.f/32.f);
    g_KL[(bh*MLAND+mr)*DIM+c] = sk*(1.f/32.f);
}

// ---------------- attn2 = softmax(q_land @ k_land^T) ----------------
__global__ void attn2_kernel(){
    extern __shared__ float klt[];           // 64*257 floats
    __shared__ float qr[DIM];
    __shared__ float red[256];
    int bh = blockIdx.y, tid = threadIdx.x;
    for(int p=tid; p<MLAND*DIM; p+=256){
        int j = p>>6, c = p&63;
        klt[c*257+j] = g_KL[(bh*MLAND+j)*DIM+c];
    }
    __syncthreads();
    for(int rr=0; rr<16; rr++){
        int row = blockIdx.x*16 + rr;
        if(tid<DIM) qr[tid] = g_QL[(bh*MLAND+row)*DIM+tid];
        __syncthreads();
        float dot = 0.f;
#pragma unroll
        for(int c=0;c<DIM;c++) dot += qr[c]*klt[c*257+tid];
        red[tid]=dot; __syncthreads();
        for(int s=128;s>0;s>>=1){ if(tid<s) red[tid]=fmaxf(red[tid],red[tid+s]); __syncthreads(); }
        float mx = red[0]; __syncthreads();
        float e = expf(dot-mx);
        red[tid]=e; __syncthreads();
        for(int s=128;s>0;s>>=1){ if(tid<s) red[tid]+=red[tid+s]; __syncthreads(); }
        float sm = red[0]; __syncthreads();
        g_A2[((size_t)bh*MLAND+row)*MLAND+tid] = e/sm;
    }
}

// ---------------- per-bh max row-sum / max col-sum ----------------
__global__ void colrow_kernel(){
    __shared__ float red[256];
    int bh = blockIdx.x, tid = threadIdx.x;
    const float* A = g_A2 + (size_t)bh*MLAND*MLAND;
    float cs=0.f, rs=0.f;
    for(int i=0;i<MLAND;i++) cs += A[(size_t)i*MLAND+tid];
    for(int j=0;j<MLAND;j++) rs += A[(size_t)tid*MLAND+j];
    red[tid]=cs; __syncthreads();
    for(int s=128;s>0;s>>=1){ if(tid<s) red[tid]=fmaxf(red[tid],red[tid+s]); __syncthreads(); }
    if(tid==0) g_cmax[bh]=red[0];
    __syncthreads();
    red[tid]=rs; __syncthreads();
    for(int s=128;s>0;s>>=1){ if(tid<s) red[tid]=fmaxf(red[tid],red[tid+s]); __syncthreads(); }
    if(tid==0) g_rmax[bh]=red[0];
}

// ---------------- z0 = x^T * inv (coalesced transpose) ----------------
__global__ void zinit_kernel(){
    __shared__ float tile[64*65];
    int bh = blockIdx.z;
    int i0 = blockIdx.x*64, j0 = blockIdx.y*64;
    int tid = threadIdx.x;
#pragma unroll
    for(int rep=0; rep<16; rep++){
        int p = rep*256+tid; int r = p>>6, c = p&63;
        tile[r*65+c] = g_A2[((size_t)bh*MLAND + i0+r)*MLAND + j0+c];
    }
    __syncthreads();
    float mr=0.f, mc=0.f;
#pragma unroll
    for(int t=0;t<BH;t++){ mr=fmaxf(mr,g_rmax[t]); mc=fmaxf(mc,g_cmax[t]); }
    float inv = 1.f/(mr*mc);
#pragma unroll
    for(int rep=0; rep<16; rep++){
        int p = rep*256+tid; int r = p>>6, c = p&63;
        g_Z[((size_t)bh*MLAND + j0+r)*MLAND + i0+c] = tile[c*65+r]*inv;
    }
}

// ---------------- batched 256^3 GEMM: C = dg*I + s*(A@B) + tt*A  (FFMA2) ----------------
__global__ void mmex_kernel(const float* __restrict__ A, const float* __restrict__ B,
                            float* __restrict__ C, float s, float dg, float tt){
    __shared__ float As[16][66];     // [k][i]
    __shared__ float Bs[16][66];     // [k][j]
    int bh = blockIdx.z;
    A += (size_t)bh*MLAND*MLAND; B += (size_t)bh*MLAND*MLAND; C += (size_t)bh*MLAND*MLAND;
    int i0 = blockIdx.x*64, j0 = blockIdx.y*64;
    int tid = threadIdx.x, tx = tid&15, ty = tid>>4;
    int tx4 = tx*4, ty4 = ty*4;
    ull acc2[2][4] = {};             // [row-pair][col]: (row ty4+2p, row ty4+2p+1)
    for(int kk=0; kk<MLAND; kk+=16){
#pragma unroll
        for(int rep=0; rep<4; rep++){
            int p = rep*256+tid;
            int i = p>>4, kq = p&15;
            As[kq][i] = A[(size_t)(i0+i)*MLAND + kk + kq];
            int kb = p>>6, j = p&63;
            Bs[kb][j] = B[(size_t)(kk+kb)*MLAND + j0 + j];
        }
        __syncthreads();
#pragma unroll
        for(int kq=0; kq<16; kq++){
            ull a01 = ld64s(&As[kq][ty4]);
            ull a23 = ld64s(&As[kq][ty4+2]);
            ull bd0 = dup2(Bs[kq][tx4+0]);
            ull bd1 = dup2(Bs[kq][tx4+1]);
            ull bd2 = dup2(Bs[kq][tx4+2]);
            ull bd3 = dup2(Bs[kq][tx4+3]);
            FMA2(acc2[0][0], a01, bd0, acc2[0][0]);
            FMA2(acc2[0][1], a01, bd1, acc2[0][1]);
            FMA2(acc2[0][2], a01, bd2, acc2[0][2]);
            FMA2(acc2[0][3], a01, bd3, acc2[0][3]);
            FMA2(acc2[1][0], a23, bd0, acc2[1][0]);
            FMA2(acc2[1][1], a23, bd1, acc2[1][1]);
            FMA2(acc2[1][2], a23, bd2, acc2[1][2]);
            FMA2(acc2[1][3], a23, bd3, acc2[1][3]);
        }
        __syncthreads();
    }
#pragma unroll
    for(int p=0;p<2;p++){
        float lo[4], hi[4];
#pragma unroll
        for(int c=0;c<4;c++) unpk(acc2[p][c], lo[c], hi[c]);
#pragma unroll
        for(int h=0;h<2;h++){
            int gi = i0 + ty4 + 2*p + h;
            const float* rowv = h ? hi : lo;
            float o[4];
#pragma unroll
            for(int c=0;c<4;c++){
                o[c] = s*rowv[c];
                if(gi == j0+tx4+c) o[c] += dg;
            }
            if(tt != 0.f){
                float4 a4 = *reinterpret_cast<const float4*>(&A[(size_t)gi*MLAND + j0 + tx4]);
                o[0] += tt*a4.x; o[1] += tt*a4.y; o[2] += tt*a4.z; o[3] += tt*a4.w;
            }
            *reinterpret_cast<float4*>(&C[(size_t)gi*MLAND + j0 + tx4]) = make_float4(o[0],o[1],o[2],o[3]);
        }
    }
}

// ---------------- sim3 flash (FFMA2): partials over a key split ----------------
// grid (4 qblk, NSPLIT, BH), 256 threads, dyn smem 4*64*66 floats
__global__ void flash3_kernel(const float* __restrict__ k, const float* __restrict__ v){
    extern __shared__ float sm_[];
    float* qs = sm_;              // [c][i] 64x66
    float* kt = qs + 64*66;       // [c][j]
    float* vs = kt + 64*66;       // [j][d]
    float* Ps = vs + 64*66;       // [j][i]
    int qb = blockIdx.x, sp = blockIdx.y, bh = blockIdx.z;
    int tid = threadIdx.x, tx = tid&15, ty = tid>>4;
    int tx4 = tx*4, ty4 = ty*4;
#pragma unroll
    for(int rep=0; rep<16; rep++){
        int p = rep*256+tid; int r = p>>6, c = p&63;
        qs[c*66+r] = g_QL[((size_t)bh*MLAND + qb*64 + r)*DIM + c];
    }
    float m[4], l[4];
    ull acc2[2][4] = {};          // [row-pair][col]
#pragma unroll
    for(int r=0;r<4;r++){ m[r]=-1e30f; l[r]=0.f; }
    for(int t=0; t<SPLEN/64; t++){
        int j0 = sp*SPLEN + t*64;
#pragma unroll
        for(int rep=0; rep<16; rep++){
            int p = rep*256+tid; int r = p>>6, c = p&63;
            kt[c*66+r] = k[((size_t)bh*NSEQ + j0+r)*DIM + c];
            vs[r*66+c] = v[((size_t)bh*NSEQ + j0+r)*DIM + c];
        }
        __syncthreads();
        ull s2[2][4] = {};
#pragma unroll 8
        for(int c=0;c<DIM;c++){
            ull a01 = ld64s(&qs[c*66+ty4]);
            ull a23 = ld64s(&qs[c*66+ty4+2]);
            ull bd0 = dup2(kt[c*66+tx4+0]);
            ull bd1 = dup2(kt[c*66+tx4+1]);
            ull bd2 = dup2(kt[c*66+tx4+2]);
            ull bd3 = dup2(kt[c*66+tx4+3]);
            FMA2(s2[0][0], a01, bd0, s2[0][0]);
            FMA2(s2[0][1], a01, bd1, s2[0][1]);
            FMA2(s2[0][2], a01, bd2, s2[0][2]);
            FMA2(s2[0][3], a01, bd3, s2[0][3]);
            FMA2(s2[1][0], a23, bd0, s2[1][0]);
            FMA2(s2[1][1], a23, bd1, s2[1][1]);
            FMA2(s2[1][2], a23, bd2, s2[1][2]);
            FMA2(s2[1][3], a23, bd3, s2[1][3]);
        }
        float s[4][4];
#pragma unroll
        for(int p=0;p<2;p++)
#pragma unroll
            for(int cc=0;cc<4;cc++) unpk(s2[p][cc], s[2*p][cc], s[2*p+1][cc]);
        float scale[4];
#pragma unroll
        for(int r=0;r<4;r++){
            float tmax = fmaxf(fmaxf(s[r][0],s[r][1]), fmaxf(s[r][2],s[r][3]));
#pragma unroll
            for(int o=1;o<16;o<<=1) tmax = fmaxf(tmax, __shfl_xor_sync(0xffffffffu, tmax, o));
            float mn = fmaxf(m[r], tmax);
            scale[r] = expf(m[r]-mn);
            float p0[4], rs = 0.f;
#pragma unroll
            for(int cc=0;cc<4;cc++){ p0[cc] = expf(s[r][cc]-mn); rs += p0[cc]; }
#pragma unroll
            for(int o=1;o<16;o<<=1) rs += __shfl_xor_sync(0xffffffffu, rs, o);
            l[r] = l[r]*scale[r] + rs;
            m[r] = mn;
#pragma unroll
            for(int cc=0;cc<4;cc++) Ps[(tx4+cc)*66 + ty4+r] = p0[cc];
        }
#pragma unroll
        for(int p=0;p<2;p++){
            ull sc = pk2(scale[2*p], scale[2*p+1]);
#pragma unroll
            for(int cc=0;cc<4;cc++) MUL2(acc2[p][cc], acc2[p][cc], sc);
        }
        __syncthreads();
#pragma unroll 4
        for(int j=0;j<64;j++){
            ull a01 = ld64s(&Ps[j*66+ty4]);
            ull a23 = ld64s(&Ps[j*66+ty4+2]);
            ull bd0 = dup2(vs[j*66+tx4+0]);
            ull bd1 = dup2(vs[j*66+tx4+1]);
            ull bd2 = dup2(vs[j*66+tx4+2]);
            ull bd3 = dup2(vs[j*66+tx4+3]);
            FMA2(acc2[0][0], a01, bd0, acc2[0][0]);
            FMA2(acc2[0][1], a01, bd1, acc2[0][1]);
            FMA2(acc2[0][2], a01, bd2, acc2[0][2]);
            FMA2(acc2[0][3], a01, bd3, acc2[0][3]);
            FMA2(acc2[1][0], a23, bd0, acc2[1][0]);
            FMA2(acc2[1][1], a23, bd1, acc2[1][1]);
            FMA2(acc2[1][2], a23, bd2, acc2[1][2]);
            FMA2(acc2[1][3], a23, bd3, acc2[1][3]);
        }
        __syncthreads();
    }
    int base = ((bh*4+qb)*NSPLIT + sp);
    float accs[4][4];
#pragma unroll
    for(int p=0;p<2;p++)
#pragma unroll
        for(int cc=0;cc<4;cc++) unpk(acc2[p][cc], accs[2*p][cc], accs[2*p+1][cc]);
#pragma unroll
    for(int r=0;r<4;r++){
        int i = ty4+r;
        *reinterpret_cast<float4*>(&g_pacc[((size_t)base*64 + i)*64 + tx4]) =
            make_float4(accs[r][0],accs[r][1],accs[r][2],accs[r][3]);
        if(tx==0){ g_pm[base*64+i]=m[r]; g_pl[base*64+i]=l[r]; }
    }
}

// ---------------- merge flash partials -> g_T ----------------
__global__ void merge3_kernel(){
    int bq = blockIdx.x;
    int tid = threadIdx.x;
    int i = tid>>2, g = tid&3;
    float M = -1e30f;
#pragma unroll
    for(int s=0;s<NSPLIT;s++) M = fmaxf(M, g_pm[(bq*NSPLIT+s)*64 + i]);
    float L = 0.f;
#pragma unroll
    for(int s=0;s<NSPLIT;s++) L += g_pl[(bq*NSPLIT+s)*64 + i]*expf(g_pm[(bq*NSPLIT+s)*64+i]-M);
    float invL = 1.f/L;
    float o[16];
#pragma unroll
    for(int d=0;d<16;d++) o[d]=0.f;
#pragma unroll
    for(int s=0;s<NSPLIT;s++){
        float w = expf(g_pm[(bq*NSPLIT+s)*64+i]-M);
        const float* pa = &g_pacc[((size_t)(bq*NSPLIT+s)*64 + i)*64 + g*16];
#pragma unroll
        for(int d=0;d<16;d++) o[d] += w*pa[d];
    }
    int bh = bq>>2, qb = bq&3;
    float* To = &g_T[((size_t)bh*MLAND + qb*64 + i)*DIM + g*16];
#pragma unroll
    for(int d=0;d<16;d++) To[d] = o[d]*invL;
}

// ---------------- C[rows,64] = A[rows,K] @ B[K,64] (W2 = Z @ T) ----------------
__global__ void ab_kernel(const float* __restrict__ A, const float* __restrict__ B,
                          float* __restrict__ C, int rows, int K){
    __shared__ float Vs[64][64];
    __shared__ float Ss[32][64];
    int bh = blockIdx.y;
    const float* Ab = A + (size_t)bh*rows*K;
    const float* Bb = B + (size_t)bh*K*DIM;
    float*       Cb = C + (size_t)bh*rows*DIM;
    int r0 = blockIdx.x*32;
    int tid = threadIdx.x;
    int d = tid&31, ig = tid>>5;
    float acc[4][2] = {};
    for(int kt=0; kt<K; kt+=64){
#pragma unroll
        for(int rep=0; rep<16; rep++){
            int p = rep*256+tid; int j = p>>6, c = p&63;
            Vs[j][c] = Bb[(size_t)(kt+j)*DIM + c];
        }
#pragma unroll
        for(int rep=0; rep<8; rep++){
            int p = rep*256+tid; int rr = p>>6, jj = p&63;
            Ss[rr][jj] = Ab[(size_t)(r0+rr)*K + kt + jj];
        }
        __syncthreads();
#pragma unroll 4
        for(int j=0;j<64;j++){
            float v0 = Vs[j][d], v1 = Vs[j][d+32];
#pragma unroll
            for(int r=0;r<4;r++){
                float sv = Ss[ig+8*r][j];
                acc[r][0] += sv*v0;
                acc[r][1] += sv*v1;
            }
        }
        __syncthreads();
    }
#pragma unroll
    for(int r=0;r<4;r++){
        Cb[(size_t)(r0+ig+8*r)*DIM + d]      = acc[r][0];
        Cb[(size_t)(r0+ig+8*r)*DIM + d + 32] = acc[r][1];
    }
}

// ---------------- sim1 fused (FFMA2): out = softmax(q@KL^T)@W2 + conv(v) ----------------
// grid (128, BH), 256 threads, dyn smem (64*257 + 2*64*66) floats
__global__ void fused1_kernel(const float* __restrict__ q, const float* __restrict__ v,
                              const float* __restrict__ cw, float* __restrict__ out){
    extern __shared__ float sm_[];
    float* Ss = sm_;              // [i][j] 64x257
    float* As = Ss + 64*257;      // [c][i] 64x66
    float* Bs = As + 64*66;       // 64x66
    float* Vv = As;               // conv reuse: 96x66 fits in As+Bs (8448)
    __shared__ float ws[KW];
    int bh = blockIdx.y;
    int r0 = blockIdx.x*64;
    int tid = threadIdx.x, tx = tid&15, ty = tid>>4;
    int tx4 = tx*4, ty4 = ty*4;
    if(tid<KW) ws[tid] = cw[(bh&7)*KW + tid];
#pragma unroll
    for(int rep=0; rep<16; rep++){
        int p = rep*256+tid; int r = p>>6, c = p&63;
        As[c*66+r] = q[((size_t)bh*NSEQ + r0+r)*DIM + c];
    }
    // phase 1: S = q @ KL^T (pack over rows)
    for(int jt=0; jt<4; jt++){
#pragma unroll
        for(int rep=0; rep<16; rep++){
            int p = rep*256+tid; int r = p>>6, c = p&63;
            Bs[c*66+r] = g_KL[((size_t)bh*MLAND + jt*64 + r)*DIM + c];
        }
        __syncthreads();
        ull s2[2][4] = {};
#pragma unroll 8
        for(int c=0;c<DIM;c++){
            ull a01 = ld64s(&As[c*66+ty4]);
            ull a23 = ld64s(&As[c*66+ty4+2]);
            ull bd0 = dup2(Bs[c*66+tx4+0]);
            ull bd1 = dup2(Bs[c*66+tx4+1]);
            ull bd2 = dup2(Bs[c*66+tx4+2]);
            ull bd3 = dup2(Bs[c*66+tx4+3]);
            FMA2(s2[0][0], a01, bd0, s2[0][0]);
            FMA2(s2[0][1], a01, bd1, s2[0][1]);
            FMA2(s2[0][2], a01, bd2, s2[0][2]);
            FMA2(s2[0][3], a01, bd3, s2[0][3]);
            FMA2(s2[1][0], a23, bd0, s2[1][0]);
            FMA2(s2[1][1], a23, bd1, s2[1][1]);
            FMA2(s2[1][2], a23, bd2, s2[1][2]);
            FMA2(s2[1][3], a23, bd3, s2[1][3]);
        }
#pragma unroll
        for(int p=0;p<2;p++)
#pragma unroll
            for(int cc=0;cc<4;cc++){
                float lo, hi;
                unpk(s2[p][cc], lo, hi);
                Ss[(ty4+2*p  )*257 + jt*64 + tx4+cc] = lo;
                Ss[(ty4+2*p+1)*257 + jt*64 + tx4+cc] = hi;
            }
        __syncthreads();
    }
    // phase 2: row softmax (4 threads per row)
    {
        int row = tid>>2, l4 = tid&3;
        float mx = -1e30f;
#pragma unroll
        for(int t=0;t<64;t++) mx = fmaxf(mx, Ss[row*257 + l4 + 4*t]);
        mx = fmaxf(mx, __shfl_xor_sync(0xffffffffu, mx, 1));
        mx = fmaxf(mx, __shfl_xor_sync(0xffffffffu, mx, 2));
        float sm = 0.f;
#pragma unroll
        for(int t=0;t<64;t++){
            int idx = row*257 + l4 + 4*t;
            float e = expf(Ss[idx]-mx);
            Ss[idx] = e;
            sm += e;
        }
        sm += __shfl_xor_sync(0xffffffffu, sm, 1);
        sm += __shfl_xor_sync(0xffffffffu, sm, 2);
        float inv = 1.f/sm;
#pragma unroll
        for(int t=0;t<64;t++) Ss[row*257 + l4 + 4*t] *= inv;
    }
    __syncthreads();
    // phase 3: out = P @ W2 (pack over cols)
    ull oacc2[4][2] = {};
    for(int jt=0; jt<4; jt++){
#pragma unroll
        for(int rep=0; rep<16; rep++){
            int p = rep*256+tid; int r = p>>6, c = p&63;
            Bs[r*66+c] = g_W2[((size_t)bh*MLAND + jt*64 + r)*DIM + c];
        }
        __syncthreads();
#pragma unroll 4
        for(int jj=0;jj<64;jj++){
            ull b01 = ld64s(&Bs[jj*66+tx4]);
            ull b23 = ld64s(&Bs[jj*66+tx4+2]);
#pragma unroll
            for(int r=0;r<4;r++){
                ull ad = dup2(Ss[(ty4+r)*257 + jt*64+jj]);
                FMA2(oacc2[r][0], ad, b01, oacc2[r][0]);
                FMA2(oacc2[r][1], ad, b23, oacc2[r][1]);
            }
        }
        __syncthreads();
    }
    // phase 4: conv residual (pack over cols) + write
#pragma unroll
    for(int rep=0; rep<24; rep++){
        int p = rep*256+tid; int rr = p>>6, c = p&63;
        int gr = r0 - PADW + rr;
        Vv[rr*66+c] = (gr>=0 && gr<NSEQ) ? v[((size_t)bh*NSEQ+gr)*DIM + c] : 0.f;
    }
    __syncthreads();
    ull cacc2[4][2] = {};
#pragma unroll
    for(int kk=0; kk<KW; kk++){
        ull wd = dup2(ws[kk]);
#pragma unroll
        for(int r=0;r<4;r++){
            int i = ty4+r;
            ull v01 = ld64s(&Vv[(i+kk)*66 + tx4]);
            ull v23 = ld64s(&Vv[(i+kk)*66 + tx4+2]);
            FMA2(cacc2[r][0], wd, v01, cacc2[r][0]);
            FMA2(cacc2[r][1], wd, v23, cacc2[r][1]);
        }
    }
#pragma unroll
    for(int r=0;r<4;r++){
        int i = ty4+r;
        ull s0, s1;
        ADD2(s0, oacc2[r][0], cacc2[r][0]);
        ADD2(s1, oacc2[r][1], cacc2[r][1]);
        float x0,x1,x2,x3;
        unpk(s0,x0,x1); unpk(s1,x2,x3);
        *reinterpret_cast<float4*>(&out[((size_t)bh*NSEQ + r0 + i)*DIM + tx4]) =
            make_float4(x0,x1,x2,x3);
    }
}

// ---------------- launch (graph fork/join: sim3 overlaps pinv chain) ----------------
static cudaStream_t g_s1 = nullptr;
static cudaEvent_t  g_ev0 = nullptr, g_ev1 = nullptr;

extern "C" void kernel_launch(void* const* d_in, const int* in_sizes, int n_in,
                              void* d_out, int out_size){
    const float* q  = (const float*)d_in[0];
    const float* k  = (const float*)d_in[1];
    const float* v  = (const float*)d_in[2];
    const float* cw = (const float*)d_in[3];
    float* out = (float*)d_out;

    if(!g_s1){
        cudaStreamCreateWithFlags(&g_s1, cudaStreamNonBlocking);
        cudaEventCreateWithFlags(&g_ev0, cudaEventDisableTiming);
        cudaEventCreateWithFlags(&g_ev1, cudaEventDisableTiming);
    }

    float *pA2,*pZ,*pZ2,*pXZ,*pU,*pWm,*pT,*pW2;
    cudaGetSymbolAddress((void**)&pA2, g_A2);
    cudaGetSymbolAddress((void**)&pZ,  g_Z);
    cudaGetSymbolAddress((void**)&pZ2, g_Z2);
    cudaGetSymbolAddress((void**)&pXZ, g_XZ);
    cudaGetSymbolAddress((void**)&pU,  g_U);
    cudaGetSymbolAddress((void**)&pWm, g_Wm);
    cudaGetSymbolAddress((void**)&pT,  g_T);
    cudaGetSymbolAddress((void**)&pW2, g_W2);

    cudaFuncSetAttribute(attn2_kernel,  cudaFuncAttributeMaxDynamicSharedMemorySize, 64*257*4);
    cudaFuncSetAttribute(flash3_kernel, cudaFuncAttributeMaxDynamicSharedMemorySize, 4*64*66*4);
    cudaFuncSetAttribute(fused1_kernel, cudaFuncAttributeMaxDynamicSharedMemorySize, (64*257 + 2*64*66)*4);

    // landmarks (both branches need QL/KL)
    landmark_kernel<<<dim3(MLAND,BH), DIM>>>(q, k);

    // fork: sim3 branch on side stream
    cudaEventRecord(g_ev0, 0);
    cudaStreamWaitEvent(g_s1, g_ev0, 0);
    flash3_kernel<<<dim3(4,NSPLIT,BH), 256, 4*64*66*4, g_s1>>>(k, v);
    merge3_kernel<<<BH*4, 256, 0, g_s1>>>();
    cudaEventRecord(g_ev1, g_s1);

    // pinv branch on main stream
    attn2_kernel<<<dim3(16,BH), 256, 64*257*4>>>();
    colrow_kernel<<<BH, 256>>>();
    zinit_kernel<<<dim3(4,4,BH), 256>>>();
    float* zc = pZ; float* zn = pZ2;
    for(int it=0; it<6; it++){
        mmex_kernel<<<dim3(4,4,BH), 256>>>(pA2, zc, pXZ, 1.f,  0.f,  0.f);
        mmex_kernel<<<dim3(4,4,BH), 256>>>(pXZ, pXZ, pU, 1.f, 15.f, -7.f);
        mmex_kernel<<<dim3(4,4,BH), 256>>>(pXZ, pU, pWm, -1.f, 13.f, 0.f);
        mmex_kernel<<<dim3(4,4,BH), 256>>>(zc,  pWm, zn, 0.25f, 0.f, 0.f);
        float* tsw = zc; zc = zn; zn = tsw;
    }

    // join: ab needs both Z (main) and T (side)
    cudaStreamWaitEvent(0, g_ev1, 0);
    ab_kernel<<<dim3(MLAND/32, BH), 256>>>(zc, pT, pW2, MLAND, MLAND);

    // sim1 fused: out = softmax(q@KL^T) @ W2 + conv residual
    fused1_kernel<<<dim3(NSEQ/64, BH), 256, (64*257 + 2*64*66)*4>>>(q, v, cw, out);
}